// round 7
// baseline (speedup 1.0000x reference)
#include <cuda_runtime.h>
#include <cuda_bf16.h>
#include <cstdint>
#include <math.h>

#define B_    8
#define S_    2048
#define D_    512
#define M_    (B_*S_)
#define SCALE 0.04419417382415922f

// ---------------------------------------------------------------------------
// PTX helpers (arch-agnostic)
// ---------------------------------------------------------------------------
__device__ __forceinline__ uint32_t smem_to_u32(const void* p) {
    uint32_t a;
    asm("{ .reg .u64 t; cvta.to.shared.u64 t, %1; cvt.u32.u64 %0, t; }"
        : "=r"(a) : "l"(p));
    return a;
}
#define CP_ASYNC16(dst, src) \
    asm volatile("cp.async.cg.shared.global [%0], [%1], 16;" :: "r"(dst), "l"(src))
#define CP_COMMIT() asm volatile("cp.async.commit_group;")
#define CP_WAIT1()  asm volatile("cp.async.wait_group 1;")
#define CP_WAIT0()  asm volatile("cp.async.wait_group 0;")

__device__ __forceinline__ void ldsm4(uint32_t* r, uint32_t a) {
    asm volatile("ldmatrix.sync.aligned.m8n8.x4.shared.b16 {%0,%1,%2,%3}, [%4];"
        : "=r"(r[0]), "=r"(r[1]), "=r"(r[2]), "=r"(r[3]) : "r"(a));
}
__device__ __forceinline__ void mma16816(float* c, const uint32_t* a,
                                         uint32_t b0, uint32_t b1) {
    asm volatile("mma.sync.aligned.m16n8k16.row.col.f32.bf16.bf16.f32 "
        "{%0,%1,%2,%3}, {%4,%5,%6,%7}, {%8,%9}, {%0,%1,%2,%3};"
        : "+f"(c[0]), "+f"(c[1]), "+f"(c[2]), "+f"(c[3])
        : "r"(a[0]), "r"(a[1]), "r"(a[2]), "r"(a[3]), "r"(b0), "r"(b1));
}

// ---------------------------------------------------------------------------
// Scratch
// ---------------------------------------------------------------------------
#define AL __align__(256)
__device__ AL __nv_bfloat16 g_xh[M_*D_];
__device__ AL __nv_bfloat16 g_qh[M_*D_];
__device__ AL __nv_bfloat16 g_kh[M_*D_];
__device__ AL __nv_bfloat16 g_vth[M_*D_];
__device__ AL __nv_bfloat16 g_oh[M_*D_],  g_ol[M_*D_];
__device__ AL __nv_bfloat16 g_hh[M_*D_],  g_hl[M_*D_];
__device__ AL __nv_bfloat16 g_sch[(long long)B_*S_*S_];
__device__ AL __nv_bfloat16 g_wh[(long long)B_*S_*S_];
__device__ AL __nv_bfloat16 g_wth[6*D_*D_], g_wtl[3*D_*D_];
__device__ AL float g_att[M_*D_];
__device__ AL float g_onx[M_*D_];
__device__ AL float g_tmp[M_*D_];

// ---------------------------------------------------------------------------
// Tensor-core GEMM (unchanged from R5 core): C = alpha*(A @ B^T) (+ bias)
// ---------------------------------------------------------------------------
#define PITCH 144
#define ARRB  (128*PITCH)

template<int NPASS>
__device__ __forceinline__ void load_chunk(uint32_t sbase,
    const __nv_bfloat16* const* src, const long long* ldt, int k0, int tid)
{
    constexpr int NARR = (NPASS == 3) ? 4 : 2;
#pragma unroll
    for (int t = 0; t < NARR; ++t) {
#pragma unroll
        for (int j = 0; j < 4; ++j) {
            int idx = tid + j * 256;
            int r = idx >> 3, seg = idx & 7;
            const void* g = src[t] + (long long)r * ldt[t] + k0 + seg * 8;
            uint32_t d = sbase + t * ARRB + r * PITCH + seg * 16;
            CP_ASYNC16(d, g);
        }
    }
    CP_COMMIT();
}

template<int NPASS, int OUT_MODE, int BIAS_MODE>
__global__ void __launch_bounds__(256, (NPASS == 1) ? 2 : 1)
gemm_tc(const __nv_bfloat16* __restrict__ Ah, const __nv_bfloat16* __restrict__ Al,
        long long lda, long long sA,
        const __nv_bfloat16* __restrict__ Bh, const __nv_bfloat16* __restrict__ Bl,
        long long ldb, long long sB,
        float* __restrict__ Cf, __nv_bfloat16* __restrict__ Ch,
        __nv_bfloat16* __restrict__ Cl, long long ldc, long long sC,
        const float* __restrict__ bias, float alpha, int K)
{
    constexpr int NARR = (NPASS == 3) ? 4 : 2;
    constexpr int STAGE = NARR * ARRB;
    extern __shared__ __align__(16) char smem[];
    const uint32_t smem_base = smem_to_u32(smem);
    const int tid  = threadIdx.x;
    const int lane = tid & 31;
    const int wid  = tid >> 5;
    const int wm = wid >> 2, wn = wid & 3;
    const long long bz = blockIdx.z;
    const long long m0 = (long long)blockIdx.y * 128;
    const long long n0 = (long long)blockIdx.x * 128;

    const __nv_bfloat16* src[NARR];
    long long ldt[NARR];
    if (NPASS == 3) {
        src[0] = Ah + bz*sA + m0*lda;  src[1] = Al + bz*sA + m0*lda;
        src[2] = Bh + bz*sB + n0*ldb;  src[3] = Bl + bz*sB + n0*ldb;
        ldt[0] = lda; ldt[1] = lda; ldt[2] = ldb; ldt[3] = ldb;
    } else {
        src[0] = Ah + bz*sA + m0*lda;  src[1] = Bh + bz*sB + n0*ldb;
        ldt[0] = lda; ldt[1] = ldb;
    }

    float acc[4][4][4];
#pragma unroll
    for (int i = 0; i < 4; ++i)
#pragma unroll
        for (int j = 0; j < 4; ++j)
#pragma unroll
            for (int r = 0; r < 4; ++r) acc[i][j][r] = 0.f;

    const int q = lane >> 3, rim = lane & 7;
    const int aRow = wm * 64 + (q & 1) * 8 + rim;
    const int aKc  = (q >> 1) * 8;
    const int bRow = wn * 32 + (q & 1) * 8 + rim;
    const int bKc  = (q >> 1) * 8;

    const int nch = K >> 6;
    load_chunk<NPASS>(smem_base, src, ldt, 0, tid);

    for (int c = 0; c < nch; ++c) {
        if (c + 1 < nch) {
            load_chunk<NPASS>(smem_base + ((c + 1) & 1) * STAGE, src, ldt,
                              (c + 1) << 6, tid);
            CP_WAIT1();
        } else {
            CP_WAIT0();
        }
        __syncthreads();

        const uint32_t sb = smem_base + (c & 1) * STAGE;
        const uint32_t aH = sb;
        const uint32_t aL = sb + ARRB;
        const uint32_t bH = sb + (NPASS == 3 ? 2 : 1) * ARRB;
        const uint32_t bL = sb + 3 * ARRB;
#pragma unroll
        for (int kk = 0; kk < 4; ++kk) {
            uint32_t ah[4][4], al[4][4];
#pragma unroll
            for (int i = 0; i < 4; ++i) {
                uint32_t off = (uint32_t)(aRow + i * 16) * PITCH
                             + (uint32_t)(kk * 16 + aKc) * 2;
                ldsm4(ah[i], aH + off);
                if (NPASS == 3) ldsm4(al[i], aL + off);
            }
#pragma unroll
            for (int jp = 0; jp < 2; ++jp) {
                uint32_t offB = (uint32_t)(bRow + jp * 16) * PITCH
                              + (uint32_t)(kk * 16 + bKc) * 2;
                uint32_t bh[4];
                ldsm4(bh, bH + offB);
                if (NPASS == 3) {
                    uint32_t bl[4];
                    ldsm4(bl, bL + offB);
#pragma unroll
                    for (int i = 0; i < 4; ++i) {
                        mma16816(acc[i][2*jp],   ah[i], bh[0], bh[2]);
                        mma16816(acc[i][2*jp],   ah[i], bl[0], bl[2]);
                        mma16816(acc[i][2*jp],   al[i], bh[0], bh[2]);
                        mma16816(acc[i][2*jp+1], ah[i], bh[1], bh[3]);
                        mma16816(acc[i][2*jp+1], ah[i], bl[1], bl[3]);
                        mma16816(acc[i][2*jp+1], al[i], bh[1], bh[3]);
                    }
                } else {
#pragma unroll
                    for (int i = 0; i < 4; ++i) {
                        mma16816(acc[i][2*jp],   ah[i], bh[0], bh[2]);
                        mma16816(acc[i][2*jp+1], ah[i], bh[1], bh[3]);
                    }
                }
            }
        }
        __syncthreads();
    }

    const int g2 = lane >> 2, t4 = lane & 3;
#pragma unroll
    for (int i = 0; i < 4; ++i) {
#pragma unroll
        for (int half = 0; half < 2; ++half) {
            const long long m = m0 + wm * 64 + i * 16 + g2 + half * 8;
            float brow = 0.f;
            if (BIAS_MODE == 2) brow = bias[m];
#pragma unroll
            for (int j = 0; j < 4; ++j) {
                const long long n = n0 + wn * 32 + j * 8 + t4 * 2;
                float v0 = acc[i][j][half * 2 + 0] * alpha;
                float v1 = acc[i][j][half * 2 + 1] * alpha;
                if (BIAS_MODE == 1) { v0 += bias[n]; v1 += bias[n + 1]; }
                if (BIAS_MODE == 2) { v0 += brow;    v1 += brow; }
                const long long cb = bz * sC + m * ldc + n;
                if (OUT_MODE == 0) {
                    *(float2*)(Cf + cb) = make_float2(v0, v1);
                } else if (OUT_MODE == 2) {
                    __nv_bfloat162 h2;
                    h2.x = __float2bfloat16(v0);
                    h2.y = __float2bfloat16(v1);
                    *(__nv_bfloat162*)(Ch + cb) = h2;
                } else {
                    __nv_bfloat16 h0 = __float2bfloat16(v0);
                    __nv_bfloat16 h1 = __float2bfloat16(v1);
                    __nv_bfloat162 h2, l2;
                    h2.x = h0; h2.y = h1;
                    l2.x = __float2bfloat16(v0 - __bfloat162float(h0));
                    l2.y = __float2bfloat16(v1 - __bfloat162float(h1));
                    *(__nv_bfloat162*)(Ch + cb) = h2;
                    *(__nv_bfloat162*)(Cl + cb) = l2;
                }
            }
        }
    }
}

// ---------------------------------------------------------------------------
// fp32 -> bf16 round, float4-vectorized grid-stride
// ---------------------------------------------------------------------------
__global__ void __launch_bounds__(256)
round_kernel(const float* __restrict__ in, __nv_bfloat16* __restrict__ o, int n)
{
    int i = (blockIdx.x * 256 + threadIdx.x) * 4;
    const int stride = gridDim.x * 1024;
    for (; i < n; i += stride) {
        float4 v = *(const float4*)(in + i);
        __nv_bfloat162 h0, h1;
        h0.x = __float2bfloat16(v.x); h0.y = __float2bfloat16(v.y);
        h1.x = __float2bfloat16(v.z); h1.y = __float2bfloat16(v.w);
        *(__nv_bfloat162*)(o + i)     = h0;
        *(__nv_bfloat162*)(o + i + 2) = h1;
    }
}

// ---------------------------------------------------------------------------
// Fused weight prep: grid.z selects weight; z<3 single bf16, z>=3 hi/lo split
// ---------------------------------------------------------------------------
__global__ void __launch_bounds__(256)
wprep_kernel(const float* __restrict__ W0, const float* __restrict__ W1,
             const float* __restrict__ W2, const float* __restrict__ W3,
             const float* __restrict__ W4, const float* __restrict__ W5,
             __nv_bfloat16* __restrict__ wth, __nv_bfloat16* __restrict__ wtl)
{
    const int z = blockIdx.z;
    const float* Wsel[6] = { W0, W1, W2, W3, W4, W5 };
    const float* W = Wsel[z];
    const long long DD = (long long)D_ * D_;
    __nv_bfloat16* Th = wth + (long long)z * DD;
    __nv_bfloat16* Tl = (z >= 3) ? (wtl + (long long)(z - 3) * DD) : nullptr;

    __shared__ float tile[32][33];
    const int c0 = blockIdx.x * 32, r0 = blockIdx.y * 32;
    const int tx = threadIdx.x & 31, ty = threadIdx.x >> 5;
#pragma unroll
    for (int i = 0; i < 32; i += 8)
        tile[ty + i][tx] = W[(long long)(r0 + ty + i) * D_ + c0 + tx];
    __syncthreads();
#pragma unroll
    for (int i = 0; i < 32; i += 8) {
        float v = tile[tx][ty + i];
        __nv_bfloat16 h = __float2bfloat16(v);
        long long o = (long long)(c0 + ty + i) * D_ + r0 + tx;
        Th[o] = h;
        if (z >= 3) Tl[o] = __float2bfloat16(v - __bfloat162float(h));
    }
}

// ---------------------------------------------------------------------------
// Softmax: warp per row (2048 bf16), 8 rows/block, shfl-only reduction
// ---------------------------------------------------------------------------
__global__ void __launch_bounds__(256)
softmax_kernel(const __nv_bfloat16* __restrict__ s, __nv_bfloat16* __restrict__ w)
{
    const int row  = blockIdx.x * 8 + (threadIdx.x >> 5);
    const int lane = threadIdx.x & 31;
    const long long base = (long long)row * S_ + lane * 64;

    uint4 r[8];
#pragma unroll
    for (int i = 0; i < 8; ++i)
        r[i] = *(const uint4*)(s + base + i * 8);

    float mx = -3.4e38f;
#pragma unroll
    for (int i = 0; i < 8; ++i) {
        const __nv_bfloat162* p = (const __nv_bfloat162*)&r[i];
#pragma unroll
        for (int j = 0; j < 4; ++j) {
            float2 f = __bfloat1622float2(p[j]);
            mx = fmaxf(mx, fmaxf(f.x, f.y));
        }
    }
#pragma unroll
    for (int o = 16; o; o >>= 1) mx = fmaxf(mx, __shfl_xor_sync(0xffffffffu, mx, o));

    float sum = 0.f;
#pragma unroll
    for (int i = 0; i < 8; ++i) {
        const __nv_bfloat162* p = (const __nv_bfloat162*)&r[i];
#pragma unroll
        for (int j = 0; j < 4; ++j) {
            float2 f = __bfloat1622float2(p[j]);
            sum += __expf(f.x - mx) + __expf(f.y - mx);
        }
    }
#pragma unroll
    for (int o = 16; o; o >>= 1) sum += __shfl_xor_sync(0xffffffffu, sum, o);

    const float inv = 1.0f / sum;
#pragma unroll
    for (int i = 0; i < 8; ++i) {
        const __nv_bfloat162* p = (const __nv_bfloat162*)&r[i];
        uint4 ov;
        __nv_bfloat162* q = (__nv_bfloat162*)&ov;
#pragma unroll
        for (int j = 0; j < 4; ++j) {
            float2 f = __bfloat1622float2(p[j]);
            q[j].x = __float2bfloat16(__expf(f.x - mx) * inv);
            q[j].y = __float2bfloat16(__expf(f.y - mx) * inv);
        }
        *(uint4*)(w + base + i * 8) = ov;
    }
}

// ---------------------------------------------------------------------------
// LN kernels: warp per row (512 floats), 8 rows/block, shfl-only reduction
// ---------------------------------------------------------------------------
__global__ void __launch_bounds__(256)
add_ln_kernel(const float* __restrict__ x, const float* __restrict__ a,
              const float* __restrict__ gam, const float* __restrict__ bet,
              float* __restrict__ out, __nv_bfloat16* __restrict__ oh,
              __nv_bfloat16* __restrict__ ol)
{
    const int row  = blockIdx.x * 8 + (threadIdx.x >> 5);
    const int lane = threadIdx.x & 31;
    const long long base = (long long)row * D_ + lane * 16;

    float u[16];
    float s = 0.f, sq = 0.f;
#pragma unroll
    for (int i = 0; i < 4; ++i) {
        float4 xv = *(const float4*)(x + base + i * 4);
        float4 av = *(const float4*)(a + base + i * 4);
        u[4*i+0] = xv.x + av.x; u[4*i+1] = xv.y + av.y;
        u[4*i+2] = xv.z + av.z; u[4*i+3] = xv.w + av.w;
#pragma unroll
        for (int j = 0; j < 4; ++j) { s += u[4*i+j]; sq += u[4*i+j]*u[4*i+j]; }
    }
#pragma unroll
    for (int o = 16; o; o >>= 1) {
        s  += __shfl_xor_sync(0xffffffffu, s,  o);
        sq += __shfl_xor_sync(0xffffffffu, sq, o);
    }
    const float mean = s * (1.0f/512.0f);
    const float var  = sq * (1.0f/512.0f) - mean*mean;
    const float rstd = rsqrtf(var + 1e-5f);

#pragma unroll
    for (int i = 0; i < 4; ++i) {
        float4 gv = *(const float4*)(gam + lane*16 + i*4);
        float4 bv = *(const float4*)(bet + lane*16 + i*4);
        float o0 = (u[4*i+0]-mean)*rstd*gv.x + bv.x;
        float o1 = (u[4*i+1]-mean)*rstd*gv.y + bv.y;
        float o2 = (u[4*i+2]-mean)*rstd*gv.z + bv.z;
        float o3 = (u[4*i+3]-mean)*rstd*gv.w + bv.w;
        *(float4*)(out + base + i*4) = make_float4(o0, o1, o2, o3);
        __nv_bfloat162 h0, h1, l0, l1;
        h0.x = __float2bfloat16(o0); h0.y = __float2bfloat16(o1);
        h1.x = __float2bfloat16(o2); h1.y = __float2bfloat16(o3);
        l0.x = __float2bfloat16(o0 - __bfloat162float(h0.x));
        l0.y = __float2bfloat16(o1 - __bfloat162float(h0.y));
        l1.x = __float2bfloat16(o2 - __bfloat162float(h1.x));
        l1.y = __float2bfloat16(o3 - __bfloat162float(h1.y));
        *(__nv_bfloat162*)(oh + base + i*4)     = h0;
        *(__nv_bfloat162*)(oh + base + i*4 + 2) = h1;
        *(__nv_bfloat162*)(ol + base + i*4)     = l0;
        *(__nv_bfloat162*)(ol + base + i*4 + 2) = l1;
    }
}

__global__ void __launch_bounds__(256)
res_gelu_ln_kernel(const float* __restrict__ t, const float* __restrict__ res,
                   const float* __restrict__ gam, const float* __restrict__ bet,
                   __nv_bfloat16* __restrict__ oh, __nv_bfloat16* __restrict__ ol)
{
    const int row  = blockIdx.x * 8 + (threadIdx.x >> 5);
    const int lane = threadIdx.x & 31;
    const long long base = (long long)row * D_ + lane * 16;

    float u[16];
    float s = 0.f, sq = 0.f;
#pragma unroll
    for (int i = 0; i < 4; ++i) {
        float4 tv = *(const float4*)(t + base + i * 4);
        float4 rv = *(const float4*)(res + base + i * 4);
        float w0 = rv.x + tv.x, w1 = rv.y + tv.y, w2 = rv.z + tv.z, w3 = rv.w + tv.w;
        u[4*i+0] = 0.5f*w0*(1.0f + erff(w0*0.70710678118654752f));
        u[4*i+1] = 0.5f*w1*(1.0f + erff(w1*0.70710678118654752f));
        u[4*i+2] = 0.5f*w2*(1.0f + erff(w2*0.70710678118654752f));
        u[4*i+3] = 0.5f*w3*(1.0f + erff(w3*0.70710678118654752f));
#pragma unroll
        for (int j = 0; j < 4; ++j) { s += u[4*i+j]; sq += u[4*i+j]*u[4*i+j]; }
    }
#pragma unroll
    for (int o = 16; o; o >>= 1) {
        s  += __shfl_xor_sync(0xffffffffu, s,  o);
        sq += __shfl_xor_sync(0xffffffffu, sq, o);
    }
    const float mean = s * (1.0f/512.0f);
    const float var  = sq * (1.0f/512.0f) - mean*mean;
    const float rstd = rsqrtf(var + 1e-5f);

#pragma unroll
    for (int i = 0; i < 4; ++i) {
        float4 gv = *(const float4*)(gam + lane*16 + i*4);
        float4 bv = *(const float4*)(bet + lane*16 + i*4);
        float o0 = (u[4*i+0]-mean)*rstd*gv.x + bv.x;
        float o1 = (u[4*i+1]-mean)*rstd*gv.y + bv.y;
        float o2 = (u[4*i+2]-mean)*rstd*gv.z + bv.z;
        float o3 = (u[4*i+3]-mean)*rstd*gv.w + bv.w;
        __nv_bfloat162 h0, h1, l0, l1;
        h0.x = __float2bfloat16(o0); h0.y = __float2bfloat16(o1);
        h1.x = __float2bfloat16(o2); h1.y = __float2bfloat16(o3);
        l0.x = __float2bfloat16(o0 - __bfloat162float(h0.x));
        l0.y = __float2bfloat16(o1 - __bfloat162float(h0.y));
        l1.x = __float2bfloat16(o2 - __bfloat162float(h1.x));
        l1.y = __float2bfloat16(o3 - __bfloat162float(h1.y));
        *(__nv_bfloat162*)(oh + base + i*4)     = h0;
        *(__nv_bfloat162*)(oh + base + i*4 + 2) = h1;
        *(__nv_bfloat162*)(ol + base + i*4)     = l0;
        *(__nv_bfloat162*)(ol + base + i*4 + 2) = l1;
    }
}

// ---------------------------------------------------------------------------
// Launch sequence
// ---------------------------------------------------------------------------
#define SMEM_NP1 (2*2*ARRB)
#define SMEM_NP3 (2*4*ARRB)

extern "C" void kernel_launch(void* const* d_in, const int* in_sizes, int n_in,
                              void* d_out, int out_size)
{
    const float* x    = (const float*)d_in[0];
    const float* Wq   = (const float*)d_in[1];
    const float* bq   = (const float*)d_in[2];
    const float* Wk   = (const float*)d_in[3];
    const float* bk   = (const float*)d_in[4];
    const float* Wv   = (const float*)d_in[5];
    const float* bv   = (const float*)d_in[6];
    const float* ln0g = (const float*)d_in[7];
    const float* ln0b = (const float*)d_in[8];
    const float* W1   = (const float*)d_in[9];
    const float* b1   = (const float*)d_in[10];
    const float* ln1g = (const float*)d_in[11];
    const float* ln1b = (const float*)d_in[12];
    const float* W2   = (const float*)d_in[13];
    const float* b2   = (const float*)d_in[14];
    const float* ln2g = (const float*)d_in[15];
    const float* ln2b = (const float*)d_in[16];
    const float* W3   = (const float*)d_in[17];
    const float* b3   = (const float*)d_in[18];

    __nv_bfloat16 *xh, *qh, *kh, *vth, *oh, *ol, *hh, *hl, *sch, *wh, *wth, *wtl;
    float *att, *onx, *tmp;
    cudaGetSymbolAddress((void**)&xh,  g_xh);
    cudaGetSymbolAddress((void**)&qh,  g_qh);
    cudaGetSymbolAddress((void**)&kh,  g_kh);
    cudaGetSymbolAddress((void**)&vth, g_vth);
    cudaGetSymbolAddress((void**)&oh,  g_oh);  cudaGetSymbolAddress((void**)&ol, g_ol);
    cudaGetSymbolAddress((void**)&hh,  g_hh);  cudaGetSymbolAddress((void**)&hl, g_hl);
    cudaGetSymbolAddress((void**)&sch, g_sch); cudaGetSymbolAddress((void**)&wh, g_wh);
    cudaGetSymbolAddress((void**)&wth, g_wth); cudaGetSymbolAddress((void**)&wtl, g_wtl);
    cudaGetSymbolAddress((void**)&att, g_att);
    cudaGetSymbolAddress((void**)&onx, g_onx); cudaGetSymbolAddress((void**)&tmp, g_tmp);

    cudaFuncSetAttribute(gemm_tc<1,2,1>, cudaFuncAttributeMaxDynamicSharedMemorySize, SMEM_NP1);
    cudaFuncSetAttribute(gemm_tc<1,2,2>, cudaFuncAttributeMaxDynamicSharedMemorySize, SMEM_NP1);
    cudaFuncSetAttribute(gemm_tc<1,2,0>, cudaFuncAttributeMaxDynamicSharedMemorySize, SMEM_NP1);
    cudaFuncSetAttribute(gemm_tc<1,0,0>, cudaFuncAttributeMaxDynamicSharedMemorySize, SMEM_NP1);
    cudaFuncSetAttribute(gemm_tc<3,0,1>, cudaFuncAttributeMaxDynamicSharedMemorySize, SMEM_NP3);

    const dim3 t256(256);
    const long long DD = (long long)D_ * D_;
    const long long sSD = (long long)S_ * D_;
    const long long sSS = (long long)S_ * S_;

    // One fused weight-prep launch (z: 0=Wq 1=Wk 2=Wv single; 3..5 split)
    wprep_kernel<<<dim3(16,16,6), t256>>>(Wq, Wk, Wv, W1, W2, W3, wth, wtl);

    round_kernel<<<1184, t256>>>(x, xh, M_*D_);

    gemm_tc<1,2,1><<<dim3(4,128,1), t256, SMEM_NP1>>>(xh, nullptr, D_, 0,
        wth + 0*DD, nullptr, D_, 0, nullptr, qh, nullptr, D_, 0, bq, 1.f, D_);
    gemm_tc<1,2,1><<<dim3(4,128,1), t256, SMEM_NP1>>>(xh, nullptr, D_, 0,
        wth + 1*DD, nullptr, D_, 0, nullptr, kh, nullptr, D_, 0, bk, 1.f, D_);

    gemm_tc<1,2,2><<<dim3(128,4,1), t256, SMEM_NP1>>>(wth + 2*DD, nullptr, D_, 0,
        xh, nullptr, D_, 0, nullptr, vth, nullptr, (long long)M_, 0, bv, 1.f, D_);

    gemm_tc<1,2,0><<<dim3(16,16,B_), t256, SMEM_NP1>>>(qh, nullptr, D_, sSD,
        kh, nullptr, D_, sSD, nullptr, sch, nullptr, S_, sSS, nullptr, SCALE, D_);

    softmax_kernel<<<M_/8, t256>>>(sch, wh);

    gemm_tc<1,0,0><<<dim3(4,16,B_), t256, SMEM_NP1>>>(wh, nullptr, S_, sSS,
        vth, nullptr, (long long)M_, (long long)S_, att, nullptr, nullptr, D_, sSD,
        nullptr, 1.f, S_);

    add_ln_kernel<<<M_/8, t256>>>(x, att, ln0g, ln0b, onx, oh, ol);

    gemm_tc<3,0,1><<<dim3(4,128,1), t256, SMEM_NP3>>>(oh, ol, D_, 0,
        wth + 3*DD, wtl + 0*DD, D_, 0, tmp, nullptr, nullptr, D_, 0, b1, 1.f, D_);
    res_gelu_ln_kernel<<<M_/8, t256>>>(tmp, onx, ln1g, ln1b, hh, hl);

    gemm_tc<3,0,1><<<dim3(4,128,1), t256, SMEM_NP3>>>(hh, hl, D_, 0,
        wth + 4*DD, wtl + 1*DD, D_, 0, tmp, nullptr, nullptr, D_, 0, b2, 1.f, D_);
    res_gelu_ln_kernel<<<M_/8, t256>>>(tmp, onx, ln2g, ln2b, hh, hl);

    gemm_tc<3,0,1><<<dim3(4,128,1), t256, SMEM_NP3>>>(hh, hl, D_, 0,
        wth + 5*DD, wtl + 2*DD, D_, 0, (float*)d_out, nullptr, nullptr, D_, 0,
        b3, 1.f, D_);
}